// round 5
// baseline (speedup 1.0000x reference)
#include <cuda_runtime.h>

#define BSZ 2
#define SEQ 4096
#define NH 16
#define DP 64
#define DN 128
#define CS 64
#define NC 64
#define NPAIR 32
#define NSLICE 4
#define PW 16
#define P1_CTAS 128
#define TPB 512
#define CTPB 256

// ---------------- device scratch ----------------
__device__ float g_CB[(size_t)NC * NPAIR * CS * CS];        // 33.5 MB C·B^T
__device__ float g_h[(size_t)NC * NPAIR * DN * DP];         // 67 MB h_prev per chunk (p-major [p][n])
__device__ float g_ds[NC];
__device__ float g_err[2][NPAIR][NSLICE];
__device__ unsigned g_arrive;

// ---------------- cp.async helpers ----------------
__device__ __forceinline__ void cpa16(float* s, const float* g) {
    unsigned a = (unsigned)__cvta_generic_to_shared(s);
    asm volatile("cp.async.cg.shared.global [%0], [%1], 16;\n" :: "r"(a), "l"(g));
}
__device__ __forceinline__ void cpa4(float* s, const float* g) {
    unsigned a = (unsigned)__cvta_generic_to_shared(s);
    asm volatile("cp.async.ca.shared.global [%0], [%1], 4;\n" :: "r"(a), "l"(g));
}
#define CP_COMMIT() asm volatile("cp.async.commit_group;\n" ::: "memory")
#define CP_WAIT1()  asm volatile("cp.async.wait_group 1;\n" ::: "memory")
#define CP_WAIT0()  asm volatile("cp.async.wait_group 0;\n" ::: "memory")

// ---------------- pre-pass: lower-triangle CB tiles ----------------
__global__ void __launch_bounds__(CTPB) cb_kernel(const float* __restrict__ Cm,
                                                  const float* __restrict__ Bm) {
    if (blockIdx.x == 0 && threadIdx.x == 0) { g_arrive = 0u; }
    extern __shared__ float smem[];
    float* sC = smem;                // [64][129]
    float* sBt = smem + CS * 129;    // [64][129]
    int tile = blockIdx.x;
    int c = tile >> 5;
    int pair = tile & 31;
    int b = pair >> 4, h = pair & 15;
    size_t base = ((size_t)((size_t)b * SEQ + (size_t)c * CS) * NH + h) * DN;
    const float* Cg = Cm + base;
    const float* Bg = Bm + base;
    const int gs = NH * DN;
    for (int idx = threadIdx.x; idx < CS * DN; idx += CTPB) {
        int i = idx >> 7, n = idx & 127;
        sC[i * 129 + n] = Cg[(size_t)i * gs + n];
        sBt[i * 129 + n] = Bg[(size_t)i * gs + n];
    }
    __syncthreads();
    int t = threadIdx.x;
    if (t < 136) {
        int ti = (int)((sqrtf(8.f * (float)t + 1.f) - 1.f) * 0.5f);
        while ((ti + 1) * (ti + 2) / 2 <= t) ti++;
        while (ti * (ti + 1) / 2 > t) ti--;
        int tj = t - ti * (ti + 1) / 2;
        int i0 = ti * 4, j0 = tj * 4;
        float acc[4][4];
#pragma unroll
        for (int a = 0; a < 4; a++)
#pragma unroll
            for (int e = 0; e < 4; e++) acc[a][e] = 0.f;
#pragma unroll 4
        for (int n = 0; n < DN; n++) {
            float cr[4], br[4];
#pragma unroll
            for (int a = 0; a < 4; a++) cr[a] = sC[(i0 + a) * 129 + n];
#pragma unroll
            for (int e = 0; e < 4; e++) br[e] = sBt[(j0 + e) * 129 + n];
#pragma unroll
            for (int a = 0; a < 4; a++)
#pragma unroll
                for (int e = 0; e < 4; e++) acc[a][e] = fmaf(cr[a], br[e], acc[a][e]);
        }
        float* out = g_CB + (size_t)(c * NPAIR + pair) * CS * CS;
#pragma unroll
        for (int a = 0; a < 4; a++) {
            float4 v = make_float4(acc[a][0], acc[a][1], acc[a][2], acc[a][3]);
            *reinterpret_cast<float4*>(out + (i0 + a) * CS + j0) = v;
        }
    }
}

// ============================================================================
// PASS 1: sequential gate + h recurrence (h in registers), err, ds, h_prev out
// ============================================================================
#define O1_XW   0        // dte*X [64][16]   1024
#define O1_P    1024     // 64
#define O1_EMA  1088     // 16
#define O1_AB   1104     // 16
#define O1_BET  1120     // 16
#define O1_DS   1136     // 1
#define O1_RED  1140     // 16
#define O1_BUF0 1160
#define B1_B 0           // B tile [64][128] 8192
#define B1_X 8192        // X slice [64][16] 1024
#define B1_A 9216        // 64
#define BUF1SZ 9280
#define O1_BUF1 (O1_BUF0 + BUF1SZ)
#define SMEM1_FLOATS (O1_BUF1 + BUF1SZ)   // 19720 floats = 78880 B

__device__ __forceinline__ void p1_prefetch(
    int cc, float* buf, int b, int h, int p0, int tid,
    const float* __restrict__ X, const float* __restrict__ A,
    const float* __restrict__ Bm) {
    size_t rowbase = ((size_t)((size_t)b * SEQ + (size_t)cc * CS) * NH + h);
    const float* Bg = Bm + rowbase * DN;
    const float* Xg = X + rowbase * DP + p0;
#pragma unroll
    for (int idx = tid; idx < CS * DN / 4; idx += TPB) {
        int i = idx >> 5, n4 = idx & 31;
        cpa16(buf + B1_B + i * DN + n4 * 4, Bg + (size_t)i * (NH * DN) + n4 * 4);
    }
    if (tid < CS * PW / 4) {
        int i = tid >> 2, p4 = tid & 3;
        cpa16(buf + B1_X + i * PW + p4 * 4, Xg + (size_t)i * (NH * DP) + p4 * 4);
    }
    if (tid < CS)
        cpa4(buf + B1_A + tid, A + ((size_t)((size_t)b * SEQ + cc * CS + tid)) * NH + h);
}

__global__ void __launch_bounds__(TPB, 1) pass1_kernel(
    const float* __restrict__ X, const float* __restrict__ A,
    const float* __restrict__ Bm,
    const float* __restrict__ la, const float* __restrict__ lb,
    const float* __restrict__ ema0) {
    extern __shared__ float smem[];
    const int tid = threadIdx.x;
    const int lane = tid & 31;
    const int wid = tid >> 5;
    const int pair = blockIdx.x >> 2;
    const int slice = blockIdx.x & 3;
    const int b = pair >> 4, h = pair & 15;
    const int p0 = slice * PW;
    const int n0 = tid & 127;
    const int pl = (tid >> 7) * 4;    // p offset within slice (0,4,8,12)

    float* sXw  = smem + O1_XW;
    float* sP   = smem + O1_P;
    float* sEma = smem + O1_EMA;
    float* sAB  = smem + O1_AB;
    float* sBet = smem + O1_BET;
    float* sDS  = smem + O1_DS;
    float* sRed = smem + O1_RED;

    if (tid < NH) {
        float v = fminf(fmaxf(la[tid], -3.32f), -0.015f);
        sAB[tid] = 1.f - exp2f(v);
        float w = fminf(fmaxf(lb[tid], -2.f), 2.f);
        sBet[tid] = exp2f(w);
        sEma[tid] = ema0[tid];
    }
    float4 hreg = make_float4(0.f, 0.f, 0.f, 0.f);

    p1_prefetch(0, smem + O1_BUF0, b, h, p0, tid, X, A, Bm);
    CP_COMMIT();
    __syncthreads();

    for (int c = 0; c < NC; ++c) {
        float* cur = smem + (((c & 1) == 0) ? O1_BUF0 : O1_BUF1);
        float* nxt = smem + (((c & 1) == 0) ? O1_BUF1 : O1_BUF0);
        if (c + 1 < NC) {
            p1_prefetch(c + 1, nxt, b, h, p0, tid, X, A, Bm);
            CP_COMMIT();
            CP_WAIT1();
        } else {
            CP_WAIT0();
        }
        __syncthreads();

        // prefix scan of A (warp 0)
        if (wid == 0) {
            const float* sA = cur + B1_A;
            float v0 = sA[2 * lane], v1 = sA[2 * lane + 1];
            float s = v0 + v1;
#pragma unroll
            for (int o = 1; o < 32; o <<= 1) {
                float t = __shfl_up_sync(0xffffffffu, s, o);
                if (lane >= o) s += t;
            }
            sP[2 * lane] = s - v1;
            sP[2 * lane + 1] = s;
        }

        // gate
        if (c > 0) {
            if (tid == 0) {
                unsigned v;
                unsigned target = (unsigned)c * (unsigned)P1_CTAS;
                do {
                    asm volatile("ld.acquire.gpu.global.u32 %0, [%1];"
                                 : "=r"(v) : "l"(&g_arrive) : "memory");
                } while (v < target);
            }
            __syncthreads();
            if (wid == 0) {
                int hh = lane & 15;
                float4 ev = __ldcg((const float4*)&g_err[(c - 1) & 1][lane][0]);
                float e = ((ev.x + ev.y) + (ev.z + ev.w)) * (1.f / (float)(DN * DP));
                float e0 = __shfl_sync(0xffffffffu, e, hh);
                float e1 = __shfl_sync(0xffffffffu, e, hh + 16);
                float emn = 0.99f * sEma[hh] + 0.01f * (0.5f * (e0 + e1));
                __syncwarp();
                if (lane < 16) sEma[hh] = emn;
                __syncwarp();
                float nrm = e / (emn + 1e-6f);
                float boost = fmaxf(tanhf(sBet[hh] * nrm), 0.f);
                float ab = sAB[hh];
                float alpha = fminf(fmaxf(ab + (1.f - ab) * boost, 0.01f), 0.999f);
                float oma = 1.f - alpha;
#pragma unroll
                for (int o = 16; o; o >>= 1) oma += __shfl_xor_sync(0xffffffffu, oma, o);
                if (lane == 0) sDS[0] = oma * (1.f / 32.f);
            }
        } else {
            if (tid == 0) sDS[0] = 1.f;
        }
        __syncthreads();

        const float dsv = sDS[0];
        const float pT = sP[CS - 1];
        // dte-weighted X
        {
            const float* sX = cur + B1_X;
#pragma unroll
            for (int k = tid; k < CS * PW; k += TPB) {
                int r = k >> 4;
                sXw[k] = __expf(dsv * (pT - sP[r])) * sX[k];
            }
        }
        __syncthreads();

        // h update: h = dt*h + B^T @ (dte*X)
        float esum;
        {
            const float* sBt = cur + B1_B;
            const float* xw = sXw + pl;
            float4 c1 = make_float4(0.f, 0.f, 0.f, 0.f);
#pragma unroll 8
            for (int t = 0; t < CS; t++) {
                float b1 = sBt[t * DN + n0];
                float4 w = *(const float4*)(xw + t * PW);
                c1.x = fmaf(b1, w.x, c1.x); c1.y = fmaf(b1, w.y, c1.y);
                c1.z = fmaf(b1, w.z, c1.z); c1.w = fmaf(b1, w.w, c1.w);
            }
            float dt = __expf(dsv * pT);
            hreg.x = fmaf(dt, hreg.x, c1.x);
            hreg.y = fmaf(dt, hreg.y, c1.y);
            hreg.z = fmaf(dt, hreg.z, c1.z);
            hreg.w = fmaf(dt, hreg.w, c1.w);
            esum = c1.x * c1.x + c1.y * c1.y + c1.z * c1.z + c1.w * c1.w;
        }
        // store h_prev for chunk c+1 (p-major)
        if (c + 1 < NC) {
            float* gh = g_h + ((size_t)(c + 1) * NPAIR + pair) * (DN * DP)
                        + (size_t)(p0 + pl) * DN + n0;
            gh[0]       = hreg.x;
            gh[DN]      = hreg.y;
            gh[2 * DN]  = hreg.z;
            gh[3 * DN]  = hreg.w;
        }
#pragma unroll
        for (int o = 16; o; o >>= 1) esum += __shfl_xor_sync(0xffffffffu, esum, o);
        if (lane == 0) sRed[wid] = esum;
        __syncthreads();
        if (tid == 0) {
            float tot = 0.f;
#pragma unroll
            for (int w = 0; w < 16; w++) tot += sRed[w];
            asm volatile("st.global.cg.f32 [%0], %1;"
                         :: "l"(&g_err[c & 1][pair][slice]), "f"(tot) : "memory");
            unsigned d_;
            asm volatile("atom.release.gpu.global.add.u32 %0, [%1], 1;"
                         : "=r"(d_) : "l"(&g_arrive) : "memory");
        }
        if (blockIdx.x == 0 && tid == 32) g_ds[c] = dsv;
    }
}

// ============================================================================
// PASS 2: fully parallel output  Y = dfs_i * ( (CBm @ Xs) + C @ h_prev )
// ============================================================================
#define P2_C   0        // C [64][128] swizzled  8192
#define P2_H   8192     // h_prev p-major [64][128]  8192
#define P2_CB  16384    // CB [64][64] swizzled  4096
#define P2_X   20480    // Xs [64][64]           4096
#define P2_A   24576    // 64
#define P2_P   24640    // 64
#define P2_DFS 24704    // 64
#define P2_INV 24768    // 64
#define SMEM2_FLOATS 24832   // 99328 B

__global__ void __launch_bounds__(TPB, 2) pass2_kernel(
    const float* __restrict__ X, const float* __restrict__ A,
    const float* __restrict__ Cm, float* __restrict__ Y) {
    extern __shared__ float smem[];
    const int tid = threadIdx.x;
    const int lane = tid & 31;
    const int wid = tid >> 5;
    const int c = blockIdx.x >> 5;
    const int pair = blockIdx.x & 31;
    const int b = pair >> 4, h = pair & 15;
    const int yi = tid & 63;
    const int pq = tid >> 6;     // 8 p-groups of 8

    float* sC   = smem + P2_C;
    float* sH   = smem + P2_H;
    float* sCB  = smem + P2_CB;
    float* sX   = smem + P2_X;
    float* sP   = smem + P2_P;
    float* sDfs = smem + P2_DFS;
    float* sInv = smem + P2_INV;

    const size_t rowbase = ((size_t)((size_t)b * SEQ + (size_t)c * CS) * NH + h);
    const float* Cg = Cm + rowbase * DN;
    const float* Xg = X + rowbase * DP;
    const float* CBg = g_CB + (size_t)(c * NPAIR + pair) * CS * CS;
    const float* Hg = g_h + ((size_t)c * NPAIR + pair) * (DN * DP);

    // ---- async loads ----
#pragma unroll
    for (int idx = tid; idx < CS * DN / 4; idx += TPB) {
        int i = idx >> 5, g = idx & 31;
        cpa16(sC + i * DN + ((g ^ (i & 31)) << 2), Cg + (size_t)i * (NH * DN) + g * 4);
    }
    if (c > 0) {
#pragma unroll
        for (int idx = tid; idx < DN * DP / 4; idx += TPB)
            cpa16(sH + idx * 4, Hg + idx * 4);
    }
#pragma unroll
    for (int idx = tid; idx < CS * CS / 4; idx += TPB) {
        int i = idx >> 4, g4 = idx & 15;
        cpa16(sCB + i * CS + ((g4 ^ (i & 15)) << 2), CBg + i * CS + g4 * 4);
    }
#pragma unroll
    for (int idx = tid; idx < CS * DP / 4; idx += TPB) {
        int j = idx >> 4, p4 = idx & 15;
        cpa16(sX + j * DP + p4 * 4, Xg + (size_t)j * (NH * DP) + p4 * 4);
    }
    if (tid < CS)
        cpa4(smem + P2_A + tid, A + ((size_t)((size_t)b * SEQ + c * CS + tid)) * NH + h);
    CP_COMMIT();
    CP_WAIT0();
    __syncthreads();

    // ---- prefix scan of A ----
    if (wid == 0) {
        const float* sA = smem + P2_A;
        float v0 = sA[2 * lane], v1 = sA[2 * lane + 1];
        float s = v0 + v1;
#pragma unroll
        for (int o = 1; o < 32; o <<= 1) {
            float t = __shfl_up_sync(0xffffffffu, s, o);
            if (lane >= o) s += t;
        }
        sP[2 * lane] = s - v1;
        sP[2 * lane + 1] = s;
    }
    __syncthreads();

    const float dsv = (c == 0) ? 1.f : __ldg(&g_ds[c]);
    if (tid < CS) {
        float a = dsv * sP[tid];
        sDfs[tid] = __expf(a);
        sInv[tid] = __expf(-a);
    }
    __syncthreads();

    // scale X rows by inv_j; zero upper triangle of CB (swizzled addressing)
#pragma unroll
    for (int idx = tid; idx < CS * DP; idx += TPB)
        sX[idx] *= sInv[idx >> 6];
#pragma unroll
    for (int idx = tid; idx < CS * CS; idx += TPB) {
        int i = idx >> 6, j = idx & 63;
        if (j > i)
            sCB[i * CS + (((j >> 2) ^ (i & 15)) << 2) + (j & 3)] = 0.f;
    }
    __syncthreads();

    // ---- GEMMs ----
    float acc[8];
#pragma unroll
    for (int e = 0; e < 8; e++) acc[e] = 0.f;

    if (c > 0) {
        const float* crow = sC + yi * DN;
        const int sw = yi & 31;
        const float* hb = sH + pq * 8 * DN;
#pragma unroll 4
        for (int g = 0; g < 32; g++) {
            float4 cv = *(const float4*)(crow + ((g ^ sw) << 2));
#pragma unroll
            for (int e = 0; e < 8; e++) {
                float4 hv = *(const float4*)(hb + e * DN + g * 4);
                acc[e] = fmaf(cv.x, hv.x, acc[e]);
                acc[e] = fmaf(cv.y, hv.y, acc[e]);
                acc[e] = fmaf(cv.z, hv.z, acc[e]);
                acc[e] = fmaf(cv.w, hv.w, acc[e]);
            }
        }
    }
    {
        const float* cbrow = sCB + yi * CS;
        const int sw4 = yi & 15;
        const int gmax = (yi < 32) ? 8 : 16;   // warp-uniform triangular skip
        for (int g4 = 0; g4 < gmax; g4++) {
            float4 cb = *(const float4*)(cbrow + ((g4 ^ sw4) << 2));
#pragma unroll
            for (int k = 0; k < 4; k++) {
                float cbk = (k == 0) ? cb.x : (k == 1) ? cb.y : (k == 2) ? cb.z : cb.w;
                const float* xr = sX + (g4 * 4 + k) * DP + pq * 8;
                float4 x0 = *(const float4*)(xr);
                float4 x1 = *(const float4*)(xr + 4);
                acc[0] = fmaf(cbk, x0.x, acc[0]);
                acc[1] = fmaf(cbk, x0.y, acc[1]);
                acc[2] = fmaf(cbk, x0.z, acc[2]);
                acc[3] = fmaf(cbk, x0.w, acc[3]);
                acc[4] = fmaf(cbk, x1.x, acc[4]);
                acc[5] = fmaf(cbk, x1.y, acc[5]);
                acc[6] = fmaf(cbk, x1.z, acc[6]);
                acc[7] = fmaf(cbk, x1.w, acc[7]);
            }
        }
    }
    // ---- scale + store ----
    {
        float d = sDfs[yi];
        float* yo = Y + (rowbase + (size_t)yi * NH) * DP + pq * 8;
        float4 o0 = make_float4(acc[0] * d, acc[1] * d, acc[2] * d, acc[3] * d);
        float4 o1 = make_float4(acc[4] * d, acc[5] * d, acc[6] * d, acc[7] * d);
        *(float4*)yo = o0;
        *(float4*)(yo + 4) = o1;
    }
}

// ---------------- launch ----------------
extern "C" void kernel_launch(void* const* d_in, const int* in_sizes, int n_in,
                              void* d_out, int out_size) {
    const float* X  = (const float*)d_in[0];
    const float* A  = (const float*)d_in[1];
    const float* Bm = (const float*)d_in[2];
    const float* Cm = (const float*)d_in[3];
    const float* la = (const float*)d_in[4];
    const float* lb = (const float*)d_in[5];
    const float* em = (const float*)d_in[6];
    float* Y = (float*)d_out;

    const int cb_smem = 2 * CS * 129 * sizeof(float);
    const int p1_smem = SMEM1_FLOATS * sizeof(float);
    const int p2_smem = SMEM2_FLOATS * sizeof(float);
    cudaFuncSetAttribute(cb_kernel, cudaFuncAttributeMaxDynamicSharedMemorySize, cb_smem);
    cudaFuncSetAttribute(pass1_kernel, cudaFuncAttributeMaxDynamicSharedMemorySize, p1_smem);
    cudaFuncSetAttribute(pass2_kernel, cudaFuncAttributeMaxDynamicSharedMemorySize, p2_smem);

    cb_kernel<<<NC * NPAIR, CTPB, cb_smem>>>(Cm, Bm);
    pass1_kernel<<<P1_CTAS, TPB, p1_smem>>>(X, A, Bm, la, lb, em);
    pass2_kernel<<<NC * NPAIR, TPB, p2_smem>>>(X, A, Cm, Y);
}

// round 8
// speedup vs baseline: 1.2610x; 1.2610x over previous
#include <cuda_runtime.h>

#define BSZ 2
#define SEQ 4096
#define NH 16
#define DP 64
#define DN 128
#define CS 64
#define NC 64
#define NPAIR 32
#define TPB 256
#define CTPB 288
#define P2TPB 512

__device__ float g_CB[(size_t)NC * NPAIR * CS * CS];
__device__ float g_M[(size_t)NC * NPAIR * CS * CS];
__device__ float g_h[(size_t)NC * NPAIR * DN * DP];
__device__ float g_ds[NC];
__device__ float g_err[2][NPAIR];
__device__ unsigned g_arrive;

__device__ __forceinline__ void cpa16(float* s, const float* g) {
    unsigned a = (unsigned)__cvta_generic_to_shared(s);
    asm volatile("cp.async.cg.shared.global [%0], [%1], 16;\n" :: "r"(a), "l"(g));
}
__device__ __forceinline__ void cpa4(float* s, const float* g) {
    unsigned a = (unsigned)__cvta_generic_to_shared(s);
    asm volatile("cp.async.ca.shared.global [%0], [%1], 4;\n" :: "r"(a), "l"(g));
}
#define CP_COMMIT() asm volatile("cp.async.commit_group;\n" ::: "memory")
#define CP_WAIT1()  asm volatile("cp.async.wait_group 1;\n" ::: "memory")
#define CP_WAIT0()  asm volatile("cp.async.wait_group 0;\n" ::: "memory")

__device__ __forceinline__ void scan_warp0(int lane, const float* sA, float* sP) {
    float v0 = sA[2 * lane], v1 = sA[2 * lane + 1];
    float s = v0 + v1;
#pragma unroll
    for (int o = 1; o < 32; o <<= 1) {
        float t = __shfl_up_sync(0xffffffffu, s, o);
        if (lane >= o) s += t;
    }
    sP[2 * lane] = s - v1;
    sP[2 * lane + 1] = s;
}

__device__ __forceinline__ void gate_warp0(int c, int lane, float* sEma,
                                           const float* sAB, const float* sBet, float* sDS) {
    int hh = lane & 15;
    float e = __ldcg(&g_err[(c - 1) & 1][lane]) * (1.f / 8192.f);
    float e0 = __shfl_sync(0xffffffffu, e, hh);
    float e1 = __shfl_sync(0xffffffffu, e, hh + 16);
    float emn = 0.99f * sEma[hh] + 0.01f * (0.5f * (e0 + e1));
    __syncwarp();
    if (lane < 16) sEma[hh] = emn;
    __syncwarp();
    float nrm = e / (emn + 1e-6f);
    float boost = fmaxf(tanhf(sBet[hh] * nrm), 0.f);
    float ab = sAB[hh];
    float alpha = fminf(fmaxf(ab + (1.f - ab) * boost, 0.01f), 0.999f);
    float oma = 1.f - alpha;
#pragma unroll
    for (int o = 16; o; o >>= 1) oma += __shfl_xor_sync(0xffffffffu, oma, o);
    if (lane == 0) sDS[0] = oma * (1.f / 32.f);
}

__device__ __forceinline__ void wait_arrive(unsigned target) {
    unsigned v;
    do {
        asm volatile("ld.acquire.gpu.global.u32 %0, [%1];" : "=r"(v) : "l"(&g_arrive) : "memory");
    } while (v < target);
}

// ---------------- PREP: CB (lower-tri) and M = (BB^T)∘(XX^T) ----------------
__global__ void __launch_bounds__(CTPB) prep_kernel(const float* __restrict__ Cm,
                                                    const float* __restrict__ Bm,
                                                    const float* __restrict__ Xm) {
    extern __shared__ float smem[];
    float* sC = smem;                  // [64][129]
    float* sB = smem + 64 * 129;       // [64][129]
    float* sX = smem + 2 * 64 * 129;   // [64][65]
    int c = blockIdx.x >> 5, pair = blockIdx.x & 31;
    int b = pair >> 4, h = pair & 15;
    size_t rb = ((size_t)((size_t)b * SEQ + (size_t)c * CS) * NH + h);
    const float* Cg = Cm + rb * DN;
    const float* Bg = Bm + rb * DN;
    const float* Xg = Xm + rb * DP;
    for (int idx = threadIdx.x; idx < CS * DN; idx += CTPB) {
        int i = idx >> 7, n = idx & 127;
        sC[i * 129 + n] = Cg[(size_t)i * 2048 + n];
        sB[i * 129 + n] = Bg[(size_t)i * 2048 + n];
    }
    for (int idx = threadIdx.x; idx < CS * DP; idx += CTPB) {
        int i = idx >> 6, p = idx & 63;
        sX[i * 65 + p] = Xg[(size_t)i * 1024 + p];
    }
    __syncthreads();
    for (int job = threadIdx.x; job < 272; job += CTPB) {
        bool isCB = job < 136;
        int t = isCB ? job : job - 136;
        int ti = (int)((sqrtf(8.f * (float)t + 1.f) - 1.f) * 0.5f);
        while ((ti + 1) * (ti + 2) / 2 <= t) ti++;
        while (ti * (ti + 1) / 2 > t) ti--;
        int tj = t - ti * (ti + 1) / 2;
        int i0 = ti * 4, j0 = tj * 4;
        if (isCB) {
            float acc[4][4] = {};
#pragma unroll 4
            for (int n = 0; n < DN; n++) {
                float cr[4], br[4];
#pragma unroll
                for (int a = 0; a < 4; a++) cr[a] = sC[(i0 + a) * 129 + n];
#pragma unroll
                for (int e = 0; e < 4; e++) br[e] = sB[(j0 + e) * 129 + n];
#pragma unroll
                for (int a = 0; a < 4; a++)
#pragma unroll
                    for (int e = 0; e < 4; e++) acc[a][e] = fmaf(cr[a], br[e], acc[a][e]);
            }
            float* out = g_CB + (size_t)(c * NPAIR + pair) * CS * CS;
#pragma unroll
            for (int a = 0; a < 4; a++)
                *(float4*)(out + (i0 + a) * CS + j0) =
                    make_float4(acc[a][0], acc[a][1], acc[a][2], acc[a][3]);
        } else {
            float ab_[4][4] = {}, ax[4][4] = {};
#pragma unroll 4
            for (int n = 0; n < DN; n++) {
                float bi[4], bj[4];
#pragma unroll
                for (int a = 0; a < 4; a++) bi[a] = sB[(i0 + a) * 129 + n];
#pragma unroll
                for (int e = 0; e < 4; e++) bj[e] = sB[(j0 + e) * 129 + n];
#pragma unroll
                for (int a = 0; a < 4; a++)
#pragma unroll
                    for (int e = 0; e < 4; e++) ab_[a][e] = fmaf(bi[a], bj[e], ab_[a][e]);
            }
#pragma unroll 4
            for (int p = 0; p < DP; p++) {
                float xi[4], xj[4];
#pragma unroll
                for (int a = 0; a < 4; a++) xi[a] = sX[(i0 + a) * 65 + p];
#pragma unroll
                for (int e = 0; e < 4; e++) xj[e] = sX[(j0 + e) * 65 + p];
#pragma unroll
                for (int a = 0; a < 4; a++)
#pragma unroll
                    for (int e = 0; e < 4; e++) ax[a][e] = fmaf(xi[a], xj[e], ax[a][e]);
            }
            float* Mo = g_M + (size_t)(c * NPAIR + pair) * CS * CS;
#pragma unroll
            for (int a = 0; a < 4; a++)
#pragma unroll
                for (int e = 0; e < 4; e++) {
                    float m = ab_[a][e] * ax[a][e];
                    Mo[(i0 + a) * CS + (j0 + e)] = m;
                    Mo[(j0 + e) * CS + (i0 + a)] = m;
                }
        }
    }
}

// ---------------- PASS 1: 32 chain CTAs + 256 worker CTAs ----------------
// header: sP 0..63 | sEma 64 | sAB 80 | sBet 96 | sDS 112 | sRed 116 | sW 128..191 | sXw 192..703
#define HDR 704
#define CM_M 0
#define CM_A 4352          // M [64][68]
#define CBUF 4416
#define WB_B 0
#define WB_X 8192
#define WB_A 8704
#define WBUF 8768
#define SMEM1_FLOATS (HDR + 2 * WBUF)   // 18240 floats = 72960 B

__global__ void __launch_bounds__(TPB, 2) pass1_kernel(
    const float* __restrict__ X, const float* __restrict__ A,
    const float* __restrict__ Bm,
    const float* __restrict__ la, const float* __restrict__ lb,
    const float* __restrict__ ema0) {
    extern __shared__ float smem[];
    const int tid = threadIdx.x, lane = tid & 31, wid = tid >> 5;
    float* sP = smem; float* sEma = smem + 64; float* sAB = smem + 80;
    float* sBet = smem + 96; float* sDS = smem + 112; float* sRed = smem + 116;
    float* sW = smem + 128; float* sXw = smem + 192;
    if (tid < NH) {
        sAB[tid] = 1.f - exp2f(fminf(fmaxf(la[tid], -3.32f), -0.015f));
        sBet[tid] = exp2f(fminf(fmaxf(lb[tid], -2.f), 2.f));
        sEma[tid] = ema0[tid];
    }

    if (blockIdx.x < 32) {  // ======== CHAIN ========
        const int pair = blockIdx.x, b = pair >> 4, h = pair & 15;
        {
            const float* Mg = g_M + (size_t)pair * CS * CS;
            float* buf = smem + HDR;
            for (int i = tid; i < 1024; i += TPB)
                cpa16(buf + CM_M + (i >> 4) * 68 + (i & 15) * 4, Mg + (i >> 4) * 64 + (i & 15) * 4);
            if (tid < CS) cpa4(buf + CM_A + tid, A + ((size_t)b * SEQ + tid) * NH + h);
        }
        CP_COMMIT();
        __syncthreads();
        for (int c = 0; c < NC; ++c) {
            float* cur = smem + HDR + ((c & 1) ? CBUF : 0);
            float* nxt = smem + HDR + ((c & 1) ? 0 : CBUF);
            if (c + 1 < NC) {
                const float* Mg = g_M + (size_t)((c + 1) * NPAIR + pair) * CS * CS;
                for (int i = tid; i < 1024; i += TPB)
                    cpa16(nxt + CM_M + (i >> 4) * 68 + (i & 15) * 4, Mg + (i >> 4) * 64 + (i & 15) * 4);
                if (tid < CS)
                    cpa4(nxt + CM_A + tid, A + ((size_t)b * SEQ + (c + 1) * CS + tid) * NH + h);
                CP_COMMIT(); CP_WAIT1();
            } else CP_WAIT0();
            __syncthreads();
            if (wid == 0) scan_warp0(lane, cur + CM_A, sP);
            if (c > 0) {
                if (tid == 0) wait_arrive(32u * (unsigned)c);
                __syncthreads();
                if (wid == 0) gate_warp0(c, lane, sEma, sAB, sBet, sDS);
            } else if (tid == 0) sDS[0] = 1.f;
            __syncthreads();
            const float dsv = sDS[0], pT = sP[CS - 1];
            if (tid < CS) sW[tid] = __expf(dsv * (pT - sP[tid]));
            if (pair == 0 && tid == 64) g_ds[c] = dsv;
            __syncthreads();
            {   // err = w^T M w
                int r = tid & 63, seg = tid >> 6;
                const float* mrow = cur + CM_M + r * 68 + seg * 16;
                const float* ws = sW + seg * 16;
                float p = 0.f;
#pragma unroll
                for (int i = 0; i < 4; i++) {
                    float4 m = *(const float4*)(mrow + i * 4);
                    float4 w = *(const float4*)(ws + i * 4);
                    p += m.x * w.x + m.y * w.y + m.z * w.z + m.w * w.w;
                }
                p *= sW[r];
#pragma unroll
                for (int o = 16; o; o >>= 1) p += __shfl_xor_sync(0xffffffffu, p, o);
                if (lane == 0) sRed[wid] = p;
            }
            __syncthreads();
            if (tid == 0) {
                float tot = 0.f;
#pragma unroll
                for (int w = 0; w < 8; w++) tot += sRed[w];
                asm volatile("st.global.cg.f32 [%0], %1;" :: "l"(&g_err[c & 1][pair]), "f"(tot) : "memory");
                unsigned d_;
                asm volatile("atom.release.gpu.global.add.u32 %0, [%1], 1;"
                             : "=r"(d_) : "l"(&g_arrive) : "memory");
            }
        }
    } else {  // ======== WORKER ========
        const int idx = blockIdx.x - 32;
        const int pair = idx >> 3, slice = idx & 7;
        const int b = pair >> 4, h = pair & 15;
        const int p0 = slice * 8;
        const int n0 = tid & 127, pl = (tid >> 7) * 4;
        float4 hreg = make_float4(0.f, 0.f, 0.f, 0.f);
        {
            float* buf = smem + HDR;
            const float* Bg = Bm + ((size_t)b * SEQ * NH + h) * DN;
            const float* Xg = X + ((size_t)b * SEQ * NH + h) * DP + p0;
            for (int i2 = tid; i2 < 2048; i2 += TPB)
                cpa16(buf + WB_B + (i2 >> 5) * DN + (i2 & 31) * 4, Bg + (size_t)(i2 >> 5) * 2048 + (i2 & 31) * 4);
            if (tid < 128) cpa16(buf + WB_X + (tid >> 1) * 8 + (tid & 1) * 4,
                                 Xg + (size_t)(tid >> 1) * 1024 + (tid & 1) * 4);
            if (tid < CS) cpa4(buf + WB_A + tid, A + ((size_t)b * SEQ + tid) * NH + h);
        }
        CP_COMMIT();
        __syncthreads();
        for (int c = 0; c < NC; ++c) {
            float* cur = smem + HDR + ((c & 1) ? WBUF : 0);
            float* nxt = smem + HDR + ((c & 1) ? 0 : WBUF);
            if (c + 1 < NC) {
                size_t rb = ((size_t)b * SEQ + (c + 1) * CS) * NH + h;
                const float* Bg = Bm + rb * DN;
                const float* Xg = X + rb * DP + p0;
                for (int i2 = tid; i2 < 2048; i2 += TPB)
                    cpa16(nxt + WB_B + (i2 >> 5) * DN + (i2 & 31) * 4, Bg + (size_t)(i2 >> 5) * 2048 + (i2 & 31) * 4);
                if (tid < 128) cpa16(nxt + WB_X + (tid >> 1) * 8 + (tid & 1) * 4,
                                     Xg + (size_t)(tid >> 1) * 1024 + (tid & 1) * 4);
                if (tid < CS) cpa4(nxt + WB_A + tid, A + ((size_t)b * SEQ + (c + 1) * CS + tid) * NH + h);
                CP_COMMIT(); CP_WAIT1();
            } else CP_WAIT0();
            __syncthreads();
            if (wid == 0) scan_warp0(lane, cur + WB_A, sP);
            if (c > 0) {
                if (tid == 0) wait_arrive(32u * (unsigned)c);
                __syncthreads();
                if (wid == 0) gate_warp0(c, lane, sEma, sAB, sBet, sDS);
            } else if (tid == 0) sDS[0] = 1.f;
            __syncthreads();
            const float dsv = sDS[0], pT = sP[CS - 1];
#pragma unroll
            for (int k = tid; k < CS * 8; k += TPB)
                sXw[k] = __expf(dsv * (pT - sP[k >> 3])) * cur[WB_X + k];
            __syncthreads();
            {
                const float* xw = sXw + pl;
                float4 c1 = make_float4(0.f, 0.f, 0.f, 0.f);
#pragma unroll 8
                for (int t = 0; t < CS; t++) {
                    float b1 = cur[WB_B + t * DN + n0];
                    float4 w = *(const float4*)(xw + t * 8);
                    c1.x = fmaf(b1, w.x, c1.x); c1.y = fmaf(b1, w.y, c1.y);
                    c1.z = fmaf(b1, w.z, c1.z); c1.w = fmaf(b1, w.w, c1.w);
                }
                float dt = __expf(dsv * pT);
                hreg.x = fmaf(dt, hreg.x, c1.x); hreg.y = fmaf(dt, hreg.y, c1.y);
                hreg.z = fmaf(dt, hreg.z, c1.z); hreg.w = fmaf(dt, hreg.w, c1.w);
            }
            if (c + 1 < NC) {
                float* gh = g_h + ((size_t)(c + 1) * NPAIR + pair) * (DN * DP) + (size_t)(p0 + pl) * DN + n0;
                gh[0] = hreg.x; gh[DN] = hreg.y; gh[2 * DN] = hreg.z; gh[3 * DN] = hreg.w;
            }
            __syncthreads();
        }
    }
}

// ---------------- PASS 2 (round-4, + g_arrive reset) ----------------
#define P2_C 0
#define P2_H 8192
#define P2_CB 16384
#define P2_X 20480
#define P2_A 24576
#define P2_P 24640
#define P2_DFS 24704
#define P2_INV 24768
#define SMEM2_FLOATS 24832

__global__ void __launch_bounds__(P2TPB, 2) pass2_kernel(
    const float* __restrict__ X, const float* __restrict__ A,
    const float* __restrict__ Cm, float* __restrict__ Y) {
    if (blockIdx.x == 0 && threadIdx.x == 0) g_arrive = 0u;  // reset for next replay
    extern __shared__ float smem[];
    const int tid = threadIdx.x, lane = tid & 31, wid = tid >> 5;
    const int c = blockIdx.x >> 5, pair = blockIdx.x & 31;
    const int b = pair >> 4, h = pair & 15;
    const int yi = tid & 63, pq = tid >> 6;
    float* sC = smem + P2_C; float* sH = smem + P2_H; float* sCB = smem + P2_CB;
    float* sX = smem + P2_X; float* sP = smem + P2_P;
    float* sDfs = smem + P2_DFS; float* sInv = smem + P2_INV;
    const size_t rowbase = ((size_t)((size_t)b * SEQ + (size_t)c * CS) * NH + h);
    const float* Cg = Cm + rowbase * DN;
    const float* Xg = X + rowbase * DP;
    const float* CBg = g_CB + (size_t)(c * NPAIR + pair) * CS * CS;
    const float* Hg = g_h + ((size_t)c * NPAIR + pair) * (DN * DP);
#pragma unroll
    for (int idx = tid; idx < 2048; idx += P2TPB) {
        int i = idx >> 5, g = idx & 31;
        cpa16(sC + i * DN + ((g ^ (i & 31)) << 2), Cg + (size_t)i * 2048 + g * 4);
    }
    if (c > 0)
#pragma unroll
        for (int idx = tid; idx < 2048; idx += P2TPB) cpa16(sH + idx * 4, Hg + idx * 4);
#pragma unroll
    for (int idx = tid; idx < 1024; idx += P2TPB) {
        int i = idx >> 4, g4 = idx & 15;
        cpa16(sCB + i * CS + ((g4 ^ (i & 15)) << 2), CBg + i * CS + g4 * 4);
    }
#pragma unroll
    for (int idx = tid; idx < 1024; idx += P2TPB) {
        int j = idx >> 4, p4 = idx & 15;
        cpa16(sX + j * DP + p4 * 4, Xg + (size_t)j * 1024 + p4 * 4);
    }
    if (tid < CS) cpa4(smem + P2_A + tid, A + ((size_t)b * SEQ + c * CS + tid) * NH + h);
    CP_COMMIT(); CP_WAIT0();
    __syncthreads();
    if (wid == 0) scan_warp0(lane, smem + P2_A, sP);
    __syncthreads();
    const float dsv = (c == 0) ? 1.f : __ldg(&g_ds[c]);
    if (tid < CS) {
        float a = dsv * sP[tid];
        sDfs[tid] = __expf(a); sInv[tid] = __expf(-a);
    }
    __syncthreads();
#pragma unroll
    for (int idx = tid; idx < CS * DP; idx += P2TPB) sX[idx] *= sInv[idx >> 6];
#pragma unroll
    for (int idx = tid; idx < CS * CS; idx += P2TPB) {
        int i = idx >> 6, j = idx & 63;
        if (j > i) sCB[i * CS + (((j >> 2) ^ (i & 15)) << 2) + (j & 3)] = 0.f;
    }
    __syncthreads();
    float acc[8] = {};
    if (c > 0) {
        const float* crow = sC + yi * DN;
        const int sw = yi & 31;
        const float* hb = sH + pq * 8 * DN;
#pragma unroll 4
        for (int g = 0; g < 32; g++) {
            float4 cv = *(const float4*)(crow + ((g ^ sw) << 2));
#pragma unroll
            for (int e = 0; e < 8; e++) {
                float4 hv = *(const float4*)(hb + e * DN + g * 4);
                acc[e] = fmaf(cv.x, hv.x, acc[e]); acc[e] = fmaf(cv.y, hv.y, acc[e]);
                acc[e] = fmaf(cv.z, hv.z, acc[e]); acc[e] = fmaf(cv.w, hv.w, acc[e]);
            }
        }
    }
    {
        const float* cbrow = sCB + yi * CS;
        const int sw4 = yi & 15;
        const int gmax = (yi < 32) ? 8 : 16;
        for (int g4 = 0; g4 < gmax; g4++) {
            float4 cb = *(const float4*)(cbrow + ((g4 ^ sw4) << 2));
#pragma unroll
            for (int k = 0; k < 4; k++) {
                float cbk = (k == 0) ? cb.x : (k == 1) ? cb.y : (k == 2) ? cb.z : cb.w;
                const float* xr = sX + (g4 * 4 + k) * DP + pq * 8;
                float4 x0 = *(const float4*)(xr);
                float4 x1 = *(const float4*)(xr + 4);
                acc[0] = fmaf(cbk, x0.x, acc[0]); acc[1] = fmaf(cbk, x0.y, acc[1]);
                acc[2] = fmaf(cbk, x0.z, acc[2]); acc[3] = fmaf(cbk, x0.w, acc[3]);
                acc[4] = fmaf(cbk, x1.x, acc[4]); acc[5] = fmaf(cbk, x1.y, acc[5]);
                acc[6] = fmaf(cbk, x1.z, acc[6]); acc[7] = fmaf(cbk, x1.w, acc[7]);
            }
        }
    }
    {
        float d = sDfs[yi];
        float* yo = Y + (rowbase + (size_t)yi * NH) * DP + pq * 8;
        *(float4*)yo = make_float4(acc[0] * d, acc[1] * d, acc[2] * d, acc[3] * d);
        *(float4*)(yo + 4) = make_float4(acc[4] * d, acc[5] * d, acc[6] * d, acc[7] * d);
    }
}

extern "C" void kernel_launch(void* const* d_in, const int* in_sizes, int n_in,
                              void* d_out, int out_size) {
    const float* X = (const float*)d_in[0];
    const float* A = (const float*)d_in[1];
    const float* Bm = (const float*)d_in[2];
    const float* Cm = (const float*)d_in[3];
    const float* la = (const float*)d_in[4];
    const float* lb = (const float*)d_in[5];
    const float* em = (const float*)d_in[6];
    float* Y = (float*)d_out;
    const int prep_smem = (2 * 64 * 129 + 64 * 65) * sizeof(float);
    const int p1_smem = SMEM1_FLOATS * sizeof(float);
    const int p2_smem = SMEM2_FLOATS * sizeof(float);
    cudaFuncSetAttribute(prep_kernel, cudaFuncAttributeMaxDynamicSharedMemorySize, prep_smem);
    cudaFuncSetAttribute(pass1_kernel, cudaFuncAttributeMaxDynamicSharedMemorySize, p1_smem);
    cudaFuncSetAttribute(pass2_kernel, cudaFuncAttributeMaxDynamicSharedMemorySize, p2_smem);
    prep_kernel<<<NC * NPAIR, CTPB, prep_smem>>>(Cm, Bm, X);
    pass1_kernel<<<288, TPB, p1_smem>>>(X, A, Bm, la, lb, em);
    pass2_kernel<<<NC * NPAIR, P2TPB, p2_smem>>>(X, A, Cm, Y);
}